// round 2
// baseline (speedup 1.0000x reference)
#include <cuda_runtime.h>
#include <cstdint>

#define Bz   32
#define Sz   1024
#define DIN  128
#define Hz   256
#define H4   1024
#define HD2  512
#define NCTA_SCAN 128

// ---------------- static scratch (no allocations allowed) ----------------
__device__ float g_xp_f[(size_t)Sz * Bz * H4];   // 128 MB  [t][b][4H]
__device__ float g_xp_b[(size_t)Sz * Bz * H4];   // 128 MB
__device__ float g_hseq[(size_t)Sz * Bz * HD2];  // 64 MB   [t][b][512] layer output
__device__ float g_ctx [(size_t)Sz * Bz * HD2];  // 64 MB   [t][b][512] attention context
__device__ float g_hstate[2][2][Bz][Hz];         // dir, double-buffer
__device__ float g_e[Bz * Sz];
__device__ float g_invden[Bz * Sz];
__device__ unsigned g_sync;

// ---------------- generic SGEMM-NT:  C[m][n] = sum_k A[m][k] * Bw[n][k] + bias[n]
// A row offset  = (m%32)*sAb + (m/32)*sAt
// C row offset  = (m%32)*sCb + (m/32)*sCt
#define BM 128
#define BN 64
#define BK 16

__global__ __launch_bounds__(256, 2) void sgemm_nt(
    const float* __restrict__ A, const float* __restrict__ Bw,
    const float* __restrict__ bias, float* __restrict__ C,
    int K, long sAb, long sAt, long sCb, long sCt)
{
    __shared__ float As[BK][BM + 4];
    __shared__ float Bs[BK][BN + 4];
    const int tid = threadIdx.x;
    const int m0 = blockIdx.y * BM;
    const int n0 = blockIdx.x * BN;
    const int tx = tid & 15;        // n micro (4 each)
    const int ty = tid >> 4;        // m micro (8 each)
    const int lr = tid >> 2;        // 0..63
    const int lk = (tid & 3) << 2;  // k offset 0,4,8,12

    float acc[8][4];
#pragma unroll
    for (int i = 0; i < 8; i++)
#pragma unroll
        for (int j = 0; j < 4; j++) acc[i][j] = 0.0f;

    const int mA0 = m0 + lr, mA1 = m0 + lr + 64;
    const float* ap0 = A + (long)(mA0 & 31) * sAb + (long)(mA0 >> 5) * sAt + lk;
    const float* ap1 = A + (long)(mA1 & 31) * sAb + (long)(mA1 >> 5) * sAt + lk;
    const float* bp  = Bw + (long)(n0 + lr) * K + lk;

    for (int kt = 0; kt < K; kt += BK) {
        float4 va0 = *(const float4*)(ap0 + kt);
        float4 va1 = *(const float4*)(ap1 + kt);
        float4 vb  = *(const float4*)(bp  + kt);
        As[lk + 0][lr] = va0.x; As[lk + 1][lr] = va0.y;
        As[lk + 2][lr] = va0.z; As[lk + 3][lr] = va0.w;
        As[lk + 0][lr + 64] = va1.x; As[lk + 1][lr + 64] = va1.y;
        As[lk + 2][lr + 64] = va1.z; As[lk + 3][lr + 64] = va1.w;
        Bs[lk + 0][lr] = vb.x; Bs[lk + 1][lr] = vb.y;
        Bs[lk + 2][lr] = vb.z; Bs[lk + 3][lr] = vb.w;
        __syncthreads();
#pragma unroll
        for (int k = 0; k < BK; k++) {
            float4 a0 = *(const float4*)&As[k][ty * 8];
            float4 a1 = *(const float4*)&As[k][ty * 8 + 4];
            float4 b4 = *(const float4*)&Bs[k][tx * 4];
            float am[8] = {a0.x, a0.y, a0.z, a0.w, a1.x, a1.y, a1.z, a1.w};
            float bn[4] = {b4.x, b4.y, b4.z, b4.w};
#pragma unroll
            for (int i = 0; i < 8; i++)
#pragma unroll
                for (int j = 0; j < 4; j++) acc[i][j] += am[i] * bn[j];
        }
        __syncthreads();
    }
    float4 bias4 = *(const float4*)(bias + n0 + tx * 4);
#pragma unroll
    for (int i = 0; i < 8; i++) {
        int m = m0 + ty * 8 + i;
        float* cp = C + (long)(m & 31) * sCb + (long)(m >> 5) * sCt + n0 + tx * 4;
        float4 o;
        o.x = acc[i][0] + bias4.x; o.y = acc[i][1] + bias4.y;
        o.z = acc[i][2] + bias4.z; o.w = acc[i][3] + bias4.w;
        *(float4*)cp = o;
    }
}

// ---------------- activations (expf-based, accurate enough for 1e-3) ------
__device__ __forceinline__ float sigm(float x) { return 1.0f / (1.0f + __expf(-x)); }
__device__ __forceinline__ float tanh_e(float x)
{
    x = fminf(fmaxf(x, -15.0f), 15.0f);
    float e = __expf(2.0f * x);
    return (e - 1.0f) / (e + 1.0f);
}

// ---------------- persistent bidirectional LSTM scan ----------------------
// 128 CTAs: cta = dir*64 + chunk; chunk owns 4 hidden units (16 W_hh rows).
// 256 threads: 8 warps, each warp owns 2 rows; lane = r*16 + kl, kl owns a
// 16-wide k slice; W_hh rows live in registers for the whole sequence.
__global__ __launch_bounds__(256, 1) void lstm_scan(
    const float* __restrict__ whh_f, const float* __restrict__ whh_b,
    const float* __restrict__ xp_f, const float* __restrict__ xp_b,
    float* __restrict__ hseq)
{
    __shared__ float hsm[Bz][Hz];        // 32 KB staged previous h (this dir)
    __shared__ float gsm[16][Bz + 1];    // recurrent gate partials

    const int tid = threadIdx.x;
    const int cta = blockIdx.x;
    const int dir = cta >> 6;
    const int u0  = (cta & 63) << 2;
    const float* whh = dir ? whh_b : whh_f;
    const float* xp  = dir ? xp_b : xp_f;
    float* hst = &g_hstate[dir][0][0][0];

    const int w = tid >> 5, lane = tid & 31;
    const int r = lane >> 4, kl = lane & 15;
    const int rowLocal = w * 2 + r;                 // 0..15
    const int gate = rowLocal >> 2, uu = rowLocal & 3;
    const int k0 = kl << 4;

    float4 wr0, wr1, wr2, wr3;
    {
        const float* wp = whh + (size_t)(gate * Hz + u0 + uu) * Hz + k0;
        wr0 = *(const float4*)(wp + 0);
        wr1 = *(const float4*)(wp + 4);
        wr2 = *(const float4*)(wp + 8);
        wr3 = *(const float4*)(wp + 12);
    }

    const int eb = tid >> 2, eu = tid & 3;          // elementwise ownership (tid<128)
    float c_state = 0.0f;
    const float* xp_e = xp + (size_t)eb * H4 + u0 + eu;

    for (int s = 0; s < Sz; s++) {
        const int t = dir ? (Sz - 1 - s) : s;

        // ---- stage previous h into smem (zeros at s==0) ----
        float4* hd = (float4*)hsm;
        if (s == 0) {
#pragma unroll
            for (int i = 0; i < 8; i++) hd[tid + (i << 8)] = make_float4(0, 0, 0, 0);
        } else {
            const float4* src = (const float4*)(hst + ((s & 1) ^ 1) * (Bz * Hz));
#pragma unroll
            for (int i = 0; i < 8; i++) hd[tid + (i << 8)] = src[tid + (i << 8)];
        }
        // prefetch xp for the elementwise phase (DRAM latency covered by b-loop)
        float xi = 0.f, xf = 0.f, xg = 0.f, xo = 0.f;
        if (tid < 128) {
            const float* xr = xp_e + (size_t)t * (Bz * H4);
            xi = xr[0]; xf = xr[256]; xg = xr[512]; xo = xr[768];
        }
        __syncthreads();

        // ---- recurrent matvec: 16 rows x 32 batches ----
#pragma unroll 2
        for (int b = 0; b < Bz; b++) {
            const float4* hp = (const float4*)&hsm[b][k0];
            float4 h0 = hp[0], h1 = hp[1], h2 = hp[2], h3 = hp[3];
            float a0 = wr0.x * h0.x + wr0.y * h0.y + wr0.z * h0.z + wr0.w * h0.w;
            float a1 = wr1.x * h1.x + wr1.y * h1.y + wr1.z * h1.z + wr1.w * h1.w;
            float a2 = wr2.x * h2.x + wr2.y * h2.y + wr2.z * h2.z + wr2.w * h2.w;
            float a3 = wr3.x * h3.x + wr3.y * h3.y + wr3.z * h3.z + wr3.w * h3.w;
            float acc = (a0 + a1) + (a2 + a3);
            acc += __shfl_xor_sync(0xffffffffu, acc, 1);
            acc += __shfl_xor_sync(0xffffffffu, acc, 2);
            acc += __shfl_xor_sync(0xffffffffu, acc, 4);
            acc += __shfl_xor_sync(0xffffffffu, acc, 8);
            if (kl == 0) gsm[rowLocal][b] = acc;
        }
        __syncthreads();

        // ---- gates + state update (128 threads: (b, u) pairs) ----
        if (tid < 128) {
            float gi = xi + gsm[eu][eb];
            float gf = xf + gsm[4 + eu][eb];
            float gg = xg + gsm[8 + eu][eb];
            float go = xo + gsm[12 + eu][eb];
            c_state = sigm(gf) * c_state + sigm(gi) * tanh_e(gg);
            float hnew = sigm(go) * tanh_e(c_state);
            hst[(s & 1) * (Bz * Hz) + eb * Hz + u0 + eu] = hnew;
            hseq[((size_t)t * Bz + eb) * HD2 + dir * Hz + u0 + eu] = hnew;
        }

        // ---- grid barrier (release/acquire spin; all 128 CTAs resident) ----
        __threadfence();
        __syncthreads();
        if (tid == 0) {
            unsigned* sp = &g_sync;
            asm volatile("red.release.gpu.global.add.u32 [%0], %1;" :: "l"(sp), "r"(1u) : "memory");
            const unsigned target = (unsigned)(s + 1) * (unsigned)NCTA_SCAN;
            unsigned v;
            do {
                asm volatile("ld.acquire.gpu.global.u32 %0, [%1];" : "=r"(v) : "l"(sp) : "memory");
            } while (v < target);
        }
        __syncthreads();
    }
    if (cta == 0 && tid == 0) g_sync = 0;   // reset for next launch / replay
}

// ---------------- attention: scores, max, exp, cumulative denominator -----
__global__ __launch_bounds__(256, 1) void attn_score(
    const float* __restrict__ attn_w, const float* __restrict__ attn_b)
{
    const int b = blockIdx.x;
    __shared__ float wsm[HD2];
    __shared__ float ssm[Sz];
    __shared__ float dsm[Sz];
    __shared__ float red[256];
    const int tid = threadIdx.x;
    const float ab = attn_b[0];
    for (int i = tid; i < HD2; i += 256) wsm[i] = attn_w[i];
    __syncthreads();
    const int w = tid >> 5, lane = tid & 31;
    for (int t = w; t < Sz; t += 8) {
        const float4* hp = (const float4*)(g_hseq + ((size_t)t * Bz + b) * HD2 + lane * 16);
        const float4* wp = (const float4*)(wsm + lane * 16);
        float acc = 0.f;
#pragma unroll
        for (int i = 0; i < 4; i++) {
            float4 h = hp[i], ww = wp[i];
            acc += h.x * ww.x + h.y * ww.y + h.z * ww.z + h.w * ww.w;
        }
#pragma unroll
        for (int o = 16; o; o >>= 1) acc += __shfl_xor_sync(0xffffffffu, acc, o);
        if (lane == 0) ssm[t] = acc + ab;
    }
    __syncthreads();
    float m = -1e30f;
    for (int t = tid; t < Sz; t += 256) m = fmaxf(m, ssm[t]);
    red[tid] = m;
    __syncthreads();
    for (int o = 128; o; o >>= 1) {
        if (tid < o) red[tid] = fmaxf(red[tid], red[tid + o]);
        __syncthreads();
    }
    const float mx = red[0];
    for (int t = tid; t < Sz; t += 256) ssm[t] = __expf(ssm[t] - mx);
    __syncthreads();
    if (tid == 0) {
        float run = 0.f;
        for (int t = 0; t < Sz; t++) { run += ssm[t]; dsm[t] = run; }
    }
    __syncthreads();
    for (int t = tid; t < Sz; t += 256) {
        g_e[b * Sz + t] = ssm[t];
        g_invden[b * Sz + t] = 1.0f / dsm[t];
    }
}

// ---------------- cumulative context: ctx[t][b][d] = cumsum(e*h)/cumsum(e) -
__global__ __launch_bounds__(128, 8) void attn_ctx()
{
    const int b = blockIdx.x >> 2;
    const int dc = blockIdx.x & 3;
    const int d = dc * 128 + threadIdx.x;
    __shared__ float esm[Sz];
    __shared__ float ism[Sz];
    for (int t = threadIdx.x; t < Sz; t += 128) {
        esm[t] = g_e[b * Sz + t];
        ism[t] = g_invden[b * Sz + t];
    }
    __syncthreads();
    float num = 0.f;
#pragma unroll 4
    for (int t = 0; t < Sz; t++) {
        float h = g_hseq[((size_t)t * Bz + b) * HD2 + d];
        num += esm[t] * h;
        g_ctx[((size_t)t * Bz + b) * HD2 + d] = num * ism[t];
    }
}

// ---------------- host launcher -------------------------------------------
extern "C" void kernel_launch(void* const* d_in, const int* in_sizes, int n_in,
                              void* d_out, int out_size)
{
    (void)in_sizes; (void)n_in; (void)out_size;
    const float* x        = (const float*)d_in[0];
    const float* w_ih_l0f = (const float*)d_in[1];
    const float* w_hh_l0f = (const float*)d_in[2];
    const float* b_l0f    = (const float*)d_in[3];
    const float* w_ih_l0b = (const float*)d_in[4];
    const float* w_hh_l0b = (const float*)d_in[5];
    const float* b_l0b    = (const float*)d_in[6];
    const float* w_ih_l1f = (const float*)d_in[7];
    const float* w_hh_l1f = (const float*)d_in[8];
    const float* b_l1f    = (const float*)d_in[9];
    const float* w_ih_l1b = (const float*)d_in[10];
    const float* w_hh_l1b = (const float*)d_in[11];
    const float* b_l1b    = (const float*)d_in[12];
    const float* attn_w   = (const float*)d_in[13];
    const float* attn_b   = (const float*)d_in[14];
    const float* head_w   = (const float*)d_in[15];
    const float* head_b   = (const float*)d_in[16];
    float* out = (float*)d_out;

    float *xpF, *xpB, *hseq, *ctx;
    cudaGetSymbolAddress((void**)&xpF,  g_xp_f);
    cudaGetSymbolAddress((void**)&xpB,  g_xp_b);
    cudaGetSymbolAddress((void**)&hseq, g_hseq);
    cudaGetSymbolAddress((void**)&ctx,  g_ctx);

    const int M = Bz * Sz;                       // 32768
    dim3 blk(256);
    dim3 g0(H4 / BN, M / BM);                    // (16, 256)

    // layer 0 input projections: A = x [b][t][128] (b-major), C = xp [t][b][1024]
    sgemm_nt<<<g0, blk>>>(x, w_ih_l0f, b_l0f, xpF, DIN,
                          (long)Sz * DIN, DIN, (long)H4, (long)Bz * H4);
    sgemm_nt<<<g0, blk>>>(x, w_ih_l0b, b_l0b, xpB, DIN,
                          (long)Sz * DIN, DIN, (long)H4, (long)Bz * H4);
    lstm_scan<<<NCTA_SCAN, 256>>>(w_hh_l0f, w_hh_l0b, xpF, xpB, hseq);

    // layer 1 input projections: A = h0 [t][b][512] (t-major)
    sgemm_nt<<<g0, blk>>>(hseq, w_ih_l1f, b_l1f, xpF, HD2,
                          (long)HD2, (long)Bz * HD2, (long)H4, (long)Bz * H4);
    sgemm_nt<<<g0, blk>>>(hseq, w_ih_l1b, b_l1b, xpB, HD2,
                          (long)HD2, (long)Bz * HD2, (long)H4, (long)Bz * H4);
    lstm_scan<<<NCTA_SCAN, 256>>>(w_hh_l1f, w_hh_l1b, xpF, xpB, hseq);

    // attention
    attn_score<<<Bz, 256>>>(attn_w, attn_b);
    attn_ctx<<<Bz * 4, 128>>>();

    // head: A = ctx [t][b][512], C = out [b][t][128] (b-major)
    dim3 gh(DIN / BN, M / BM);                   // (2, 256)
    sgemm_nt<<<gh, blk>>>(ctx, head_w, head_b, out, HD2,
                          (long)HD2, (long)Bz * HD2, (long)Sz * DIN, (long)DIN);
}

// round 4
// speedup vs baseline: 1.2726x; 1.2726x over previous
#include <cuda_runtime.h>
#include <cstdint>

#define Bz   32
#define Sz   1024
#define DIN  128
#define Hz   256
#define H4   1024
#define HD2  512
#define NCTA_SCAN 128

// ---------------- static scratch (no allocations allowed) ----------------
__device__ float g_xp_f[(size_t)Sz * Bz * H4];   // [t][b][4H]
__device__ float g_xp_b[(size_t)Sz * Bz * H4];
__device__ float g_hseq[(size_t)Sz * Bz * HD2];  // [t][b][512]
__device__ float g_ctx [(size_t)Sz * Bz * HD2];
__device__ float g_hstate[2][2][Bz][Hz];         // dir, double-buffer
__device__ float g_e[Bz * Sz];
__device__ float g_invden[Bz * Sz];
__device__ unsigned g_flags[NCTA_SCAN];          // monotone barrier flags

// ---------------- SGEMM-NT 128x128x8, dual-output via blockIdx.z ----------
// C[m][n] = sum_k A[m][k] * Bw[n][k] + bias[n]
// A row offset = (m%32)*sAb + (m/32)*sAt ; C row offset = (m%32)*sCb + (m/32)*sCt
#define BM 128
#define BN 128

__global__ __launch_bounds__(256, 2) void sgemm_nt(
    const float* __restrict__ A,
    const float* __restrict__ Bw0, const float* __restrict__ Bw1,
    const float* __restrict__ bias0, const float* __restrict__ bias1,
    float* __restrict__ C0, float* __restrict__ C1,
    int K, long sAb, long sAt, long sCb, long sCt)
{
    const float* Bw   = blockIdx.z ? Bw1   : Bw0;
    const float* bias = blockIdx.z ? bias1 : bias0;
    float*       C    = blockIdx.z ? C1    : C0;

    __shared__ float As[8][BM + 4];
    __shared__ float Bs[8][BN + 4];

    const int tid = threadIdx.x;
    const int m0 = blockIdx.y * BM;
    const int n0 = blockIdx.x * BN;
    const int ar = tid >> 1;            // 0..127
    const int ak = (tid & 1) << 2;      // 0 or 4
    const int tx = tid & 15;            // col micro
    const int ty = tid >> 4;            // row micro (0..15)

    const int mA = m0 + ar;
    const float* apt = A + (long)(mA & 31) * sAb + (long)(mA >> 5) * sAt + ak;
    const float* bpt = Bw + (long)(n0 + ar) * K + ak;

    float acc[8][8];
#pragma unroll
    for (int i = 0; i < 8; i++)
#pragma unroll
        for (int j = 0; j < 8; j++) acc[i][j] = 0.0f;

    float4 va = *(const float4*)(apt);
    float4 vb = *(const float4*)(bpt);

    for (int kt = 0; kt < K; kt += 8) {
        As[ak + 0][ar] = va.x; As[ak + 1][ar] = va.y;
        As[ak + 2][ar] = va.z; As[ak + 3][ar] = va.w;
        Bs[ak + 0][ar] = vb.x; Bs[ak + 1][ar] = vb.y;
        Bs[ak + 2][ar] = vb.z; Bs[ak + 3][ar] = vb.w;
        __syncthreads();

        float4 va_n, vb_n;
        if (kt + 8 < K) {
            va_n = *(const float4*)(apt + kt + 8);
            vb_n = *(const float4*)(bpt + kt + 8);
        }
#pragma unroll
        for (int k = 0; k < 8; k++) {
            float4 a0 = *(const float4*)&As[k][ty * 4];
            float4 a1 = *(const float4*)&As[k][64 + ty * 4];
            float4 b0 = *(const float4*)&Bs[k][tx * 4];
            float4 b1 = *(const float4*)&Bs[k][64 + tx * 4];
            float am[8] = {a0.x, a0.y, a0.z, a0.w, a1.x, a1.y, a1.z, a1.w};
            float bn[8] = {b0.x, b0.y, b0.z, b0.w, b1.x, b1.y, b1.z, b1.w};
#pragma unroll
            for (int i = 0; i < 8; i++)
#pragma unroll
                for (int j = 0; j < 8; j++) acc[i][j] += am[i] * bn[j];
        }
        __syncthreads();
        va = va_n; vb = vb_n;
    }

    float4 biasA = *(const float4*)(bias + n0 + tx * 4);
    float4 biasB = *(const float4*)(bias + n0 + 64 + tx * 4);
    float ba[8] = {biasA.x, biasA.y, biasA.z, biasA.w, biasB.x, biasB.y, biasB.z, biasB.w};

#pragma unroll
    for (int i = 0; i < 8; i++) {
        int mi = (i < 4) ? (ty * 4 + i) : (64 + ty * 4 + i - 4);
        int m = m0 + mi;
        float* cp = C + (long)(m & 31) * sCb + (long)(m >> 5) * sCt + n0;
        float4 o0, o1;
        o0.x = acc[i][0] + ba[0]; o0.y = acc[i][1] + ba[1];
        o0.z = acc[i][2] + ba[2]; o0.w = acc[i][3] + ba[3];
        o1.x = acc[i][4] + ba[4]; o1.y = acc[i][5] + ba[5];
        o1.z = acc[i][6] + ba[6]; o1.w = acc[i][7] + ba[7];
        *(float4*)(cp + tx * 4) = o0;
        *(float4*)(cp + 64 + tx * 4) = o1;
    }
}

// ---------------- activations ---------------------------------------------
__device__ __forceinline__ float sigm(float x) { return 1.0f / (1.0f + __expf(-x)); }
__device__ __forceinline__ float tanh_e(float x)
{
    x = fminf(fmaxf(x, -15.0f), 15.0f);
    float e = __expf(2.0f * x);
    return (e - 1.0f) / (e + 1.0f);
}

// ---------------- persistent bidirectional LSTM scan ----------------------
// 128 CTAs: cta = dir*64 + chunk; chunk owns 4 hidden units (16 W_hh rows).
// 8 warps x 2 rows/warp; each lane owns an interleaved 8-float k-slice
// (float4 at 4*lane and 128+4*lane) shared by both rows -> conflict-free LDS
// and 2x register reuse. Paired 5-shfl reduction finishes both rows at once.
__global__ __launch_bounds__(256, 1) void lstm_scan(
    const float* __restrict__ whh_f, const float* __restrict__ whh_b,
    const float* __restrict__ xp_f, const float* __restrict__ xp_b,
    float* __restrict__ hseq)
{
    __shared__ float hsm[Bz * Hz];       // 32 KB staged previous h (this dir)
    __shared__ float gsm[16][Bz + 1];    // recurrent gate partials
    __shared__ unsigned s_base;

    const int tid = threadIdx.x;
    const int cta = blockIdx.x;
    const int dir = cta >> 6;
    const int u0  = (cta & 63) << 2;
    const float* whh = dir ? whh_b : whh_f;
    const float* xp  = dir ? xp_b : xp_f;
    float* hst = &g_hstate[dir][0][0][0];

    const int w = tid >> 5, lane = tid & 31;
    const int rA = w * 2;                           // local rows rA, rA+1
    // row -> W_hh row: gate = row>>2, unit = u0 + (row&3)
    const float* wpA = whh + (size_t)((rA >> 2) * Hz + u0 + (rA & 3)) * Hz;
    const float* wpB = whh + (size_t)(((rA + 1) >> 2) * Hz + u0 + ((rA + 1) & 3)) * Hz;
    const float4 wa0 = *(const float4*)(wpA + 4 * lane);
    const float4 wa1 = *(const float4*)(wpA + 128 + 4 * lane);
    const float4 wb0 = *(const float4*)(wpB + 4 * lane);
    const float4 wb1 = *(const float4*)(wpB + 128 + 4 * lane);

    const int eb = tid >> 2, eu = tid & 3;          // elementwise (tid<128)
    float c_state = 0.0f;
    const float* xp_e = xp + (size_t)eb * H4 + u0 + eu;

    if (tid == 0) s_base = g_flags[cta];            // monotone base (replay-safe)
    __syncthreads();
    const unsigned base = s_base;

    for (int s = 0; s < Sz; s++) {
        const int t = dir ? (Sz - 1 - s) : s;

        // ---- stage previous h into smem (zeros at s==0) ----
        float4* hd = (float4*)hsm;
        if (s == 0) {
#pragma unroll
            for (int i = 0; i < 8; i++) hd[tid + (i << 8)] = make_float4(0, 0, 0, 0);
        } else {
            const float4* src = (const float4*)(hst + ((s & 1) ^ 1) * (Bz * Hz));
#pragma unroll
            for (int i = 0; i < 8; i++) hd[tid + (i << 8)] = src[tid + (i << 8)];
        }
        // prefetch xp for elementwise phase
        float xi = 0.f, xf = 0.f, xg = 0.f, xo = 0.f;
        if (tid < 128) {
            const float* xr = xp_e + (size_t)t * (Bz * H4);
            xi = xr[0]; xf = xr[256]; xg = xr[512]; xo = xr[768];
        }
        __syncthreads();

        // ---- recurrent matvec: 16 rows x 32 batches ----
#pragma unroll 2
        for (int b = 0; b < Bz; b++) {
            const float4* h4 = (const float4*)(hsm + b * Hz);
            float4 c0 = h4[lane];
            float4 c1 = h4[lane + 32];
            float accA = wa0.x * c0.x + wa0.y * c0.y + wa0.z * c0.z + wa0.w * c0.w
                       + wa1.x * c1.x + wa1.y * c1.y + wa1.z * c1.z + wa1.w * c1.w;
            float accB = wb0.x * c0.x + wb0.y * c0.y + wb0.z * c0.z + wb0.w * c0.w
                       + wb1.x * c1.x + wb1.y * c1.y + wb1.z * c1.z + wb1.w * c1.w;
            float hiv = (lane & 16) ? accA : accB;
            float lov = (lane & 16) ? accB : accA;
            float val = lov + __shfl_xor_sync(0xffffffffu, hiv, 16);
            val += __shfl_xor_sync(0xffffffffu, val, 8);
            val += __shfl_xor_sync(0xffffffffu, val, 4);
            val += __shfl_xor_sync(0xffffffffu, val, 2);
            val += __shfl_xor_sync(0xffffffffu, val, 1);
            if ((lane & 15) == 0) gsm[rA + (lane >> 4)][b] = val;
        }
        __syncthreads();

        // ---- gates + state update (128 threads: (b,u) pairs) ----
        if (tid < 128) {
            float gi = xi + gsm[eu][eb];
            float gf = xf + gsm[4 + eu][eb];
            float gg = xg + gsm[8 + eu][eb];
            float go = xo + gsm[12 + eu][eb];
            c_state = sigm(gf) * c_state + sigm(gi) * tanh_e(gg);
            float hnew = sigm(go) * tanh_e(c_state);
            hst[(s & 1) * (Bz * Hz) + eb * Hz + u0 + eu] = hnew;
            hseq[((size_t)t * Bz + eb) * HD2 + dir * Hz + u0 + eu] = hnew;
        }

        // ---- grid barrier: per-CTA monotone flags (no reset, replay-safe) ----
        __threadfence();
        __syncthreads();
        const unsigned want = base + (unsigned)s + 1u;
        if (tid == 0) {
            unsigned* fp = &g_flags[cta];
            asm volatile("st.release.gpu.global.u32 [%0], %1;" :: "l"(fp), "r"(want) : "memory");
        }
        if (tid < NCTA_SCAN) {
            unsigned* fp = &g_flags[tid];
            unsigned v;
            do {
                asm volatile("ld.acquire.gpu.global.u32 %0, [%1];" : "=r"(v) : "l"(fp) : "memory");
            } while ((int)(v - want) < 0);
        }
        __syncthreads();
    }
}

// ---------------- attention: scores, max, exp, cumulative denominator -----
__global__ __launch_bounds__(256, 1) void attn_score(
    const float* __restrict__ attn_w, const float* __restrict__ attn_b)
{
    const int b = blockIdx.x;
    __shared__ float wsm[HD2];
    __shared__ float ssm[Sz];
    __shared__ float dsm[Sz];
    __shared__ float red[256];
    const int tid = threadIdx.x;
    const float ab = attn_b[0];
    for (int i = tid; i < HD2; i += 256) wsm[i] = attn_w[i];
    __syncthreads();
    const int w = tid >> 5, lane = tid & 31;
    for (int t = w; t < Sz; t += 8) {
        const float4* hp = (const float4*)(g_hseq + ((size_t)t * Bz + b) * HD2 + lane * 16);
        const float4* wp = (const float4*)(wsm + lane * 16);
        float acc = 0.f;
#pragma unroll
        for (int i = 0; i < 4; i++) {
            float4 h = hp[i], ww = wp[i];
            acc += h.x * ww.x + h.y * ww.y + h.z * ww.z + h.w * ww.w;
        }
#pragma unroll
        for (int o = 16; o; o >>= 1) acc += __shfl_xor_sync(0xffffffffu, acc, o);
        if (lane == 0) ssm[t] = acc + ab;
    }
    __syncthreads();
    float m = -1e30f;
    for (int t = tid; t < Sz; t += 256) m = fmaxf(m, ssm[t]);
    red[tid] = m;
    __syncthreads();
    for (int o = 128; o; o >>= 1) {
        if (tid < o) red[tid] = fmaxf(red[tid], red[tid + o]);
        __syncthreads();
    }
    const float mx = red[0];
    for (int t = tid; t < Sz; t += 256) ssm[t] = __expf(ssm[t] - mx);
    __syncthreads();
    if (tid == 0) {
        float run = 0.f;
        for (int t = 0; t < Sz; t++) { run += ssm[t]; dsm[t] = run; }
    }
    __syncthreads();
    for (int t = tid; t < Sz; t += 256) {
        g_e[b * Sz + t] = ssm[t];
        g_invden[b * Sz + t] = 1.0f / dsm[t];
    }
}

// ---------------- cumulative context --------------------------------------
__global__ __launch_bounds__(128, 8) void attn_ctx()
{
    const int b = blockIdx.x >> 2;
    const int dc = blockIdx.x & 3;
    const int d = dc * 128 + threadIdx.x;
    __shared__ float esm[Sz];
    __shared__ float ism[Sz];
    for (int t = threadIdx.x; t < Sz; t += 128) {
        esm[t] = g_e[b * Sz + t];
        ism[t] = g_invden[b * Sz + t];
    }
    __syncthreads();
    float num = 0.f;
#pragma unroll 4
    for (int t = 0; t < Sz; t++) {
        float h = g_hseq[((size_t)t * Bz + b) * HD2 + d];
        num += esm[t] * h;
        g_ctx[((size_t)t * Bz + b) * HD2 + d] = num * ism[t];
    }
}

// ---------------- host launcher -------------------------------------------
extern "C" void kernel_launch(void* const* d_in, const int* in_sizes, int n_in,
                              void* d_out, int out_size)
{
    (void)in_sizes; (void)n_in; (void)out_size;
    const float* x        = (const float*)d_in[0];
    const float* w_ih_l0f = (const float*)d_in[1];
    const float* w_hh_l0f = (const float*)d_in[2];
    const float* b_l0f    = (const float*)d_in[3];
    const float* w_ih_l0b = (const float*)d_in[4];
    const float* w_hh_l0b = (const float*)d_in[5];
    const float* b_l0b    = (const float*)d_in[6];
    const float* w_ih_l1f = (const float*)d_in[7];
    const float* w_hh_l1f = (const float*)d_in[8];
    const float* b_l1f    = (const float*)d_in[9];
    const float* w_ih_l1b = (const float*)d_in[10];
    const float* w_hh_l1b = (const float*)d_in[11];
    const float* b_l1b    = (const float*)d_in[12];
    const float* attn_w   = (const float*)d_in[13];
    const float* attn_b   = (const float*)d_in[14];
    const float* head_w   = (const float*)d_in[15];
    const float* head_b   = (const float*)d_in[16];
    float* out = (float*)d_out;

    float *xpF, *xpB, *hseq, *ctx;
    cudaGetSymbolAddress((void**)&xpF,  g_xp_f);
    cudaGetSymbolAddress((void**)&xpB,  g_xp_b);
    cudaGetSymbolAddress((void**)&hseq, g_hseq);
    cudaGetSymbolAddress((void**)&ctx,  g_ctx);

    const int M = Bz * Sz;                       // 32768
    dim3 blk(256);
    dim3 g0(H4 / BN, M / BM, 2);                 // (8, 256, 2) f+b fused

    // layer 0 input projections: A = x [b][t][128] (b-major), C = xp [t][b][1024]
    sgemm_nt<<<g0, blk>>>(x, w_ih_l0f, w_ih_l0b, b_l0f, b_l0b, xpF, xpB,
                          DIN, (long)Sz * DIN, DIN, (long)H4, (long)Bz * H4);
    lstm_scan<<<NCTA_SCAN, 256>>>(w_hh_l0f, w_hh_l0b, xpF, xpB, hseq);

    // layer 1 input projections: A = h0 [t][b][512] (t-major)
    sgemm_nt<<<g0, blk>>>(hseq, w_ih_l1f, w_ih_l1b, b_l1f, b_l1b, xpF, xpB,
                          HD2, (long)HD2, (long)Bz * HD2, (long)H4, (long)Bz * H4);
    lstm_scan<<<NCTA_SCAN, 256>>>(w_hh_l1f, w_hh_l1b, xpF, xpB, hseq);

    // attention
    attn_score<<<Bz, 256>>>(attn_w, attn_b);
    attn_ctx<<<Bz * 4, 128>>>();

    // head: A = ctx [t][b][512], C = out [b][t][128] (b-major)
    dim3 gh(DIN / BN, M / BM, 1);                // (1, 256, 1)
    sgemm_nt<<<gh, blk>>>(ctx, head_w, head_w, head_b, head_b, out, out,
                          HD2, (long)HD2, (long)Bz * HD2, (long)Sz * DIN, (long)DIN);
}